// round 8
// baseline (speedup 1.0000x reference)
#include <cuda_runtime.h>
#include <math.h>

#define Hn   2048
#define SEQ  2048
#define NBLK 148
#define TPB  256
#define MAXR 14      // max rows per block: ceil(2048/148)

typedef unsigned long long ull;

// ------------------------------------------------------------------
// Static device scratch (no cudaMalloc allowed)
// ------------------------------------------------------------------
__device__ float d_XF[SEQ * Hn];    // x @ Wfx^T + bfx
__device__ float d_XH[SEQ * Hn];    // x @ Whx^T + bhx
__device__ ull   d_hq[2][Hn];       // tagged hidden state: (gen<<32)|float_bits
__device__ ull   d_gq[2][Hn];       // tagged f*h
__device__ unsigned d_runbase = 1;  // tag base, advanced once per run

// atomic 8B tagged store/load (value+tag move together -> 1-RT exchange)
__device__ __forceinline__ void st_quad(ull* p, float x, unsigned tag) {
    ull q = ((ull)tag << 32) | (ull)__float_as_uint(x);
    asm volatile("st.global.cg.u64 [%0], %1;" :: "l"(p), "l"(q) : "memory");
}
__device__ __forceinline__ ull ld_quad(const ull* p) {
    ull q;
    asm volatile("ld.global.cg.u64 %0, [%1];" : "=l"(q) : "l"(p) : "memory");
    return q;
}

// poll 8 tagged quads (4 at cA.., 4 at cB..) until all carry `tag`
__device__ __forceinline__ void poll8(const ull* __restrict__ buf,
                                      int cA, int cB, unsigned tag, float* v) {
    int need = 0xFF;
    do {
#pragma unroll
        for (int j = 0; j < 8; j++) {
            if (need & (1 << j)) {
                int col = (j < 4) ? (cA + j) : (cB + j - 4);
                ull q = ld_quad(buf + col);
                if ((unsigned)(q >> 32) == tag) {
                    v[j] = __uint_as_float((unsigned)q);
                    need &= ~(1 << j);
                }
            }
        }
        if (need) __nanosleep(32);
    } while (need);
}

// ------------------------------------------------------------------
// Precompute GEMM:  C[s][n] = sum_k x[s][k] * W[n][k] + bias[n]
// ------------------------------------------------------------------
__global__ __launch_bounds__(256, 2) void mgu_gemm(
    const float* __restrict__ x,
    const float* __restrict__ Wfx, const float* __restrict__ bfx,
    const float* __restrict__ Whx, const float* __restrict__ bhx)
{
    const float* __restrict__ W    = (blockIdx.z == 0) ? Wfx : Whx;
    const float* __restrict__ bias = (blockIdx.z == 0) ? bfx : bhx;
    float* __restrict__ C          = (blockIdx.z == 0) ? d_XF : d_XH;

    __shared__ float As[16][132];
    __shared__ float Bs[16][132];

    const int bm  = blockIdx.y * 128;
    const int bn  = blockIdx.x * 128;
    const int tid = threadIdx.x;
    const int tr  = (tid >> 4) << 3;
    const int tc  = (tid & 15) << 3;

    float acc[8][8];
#pragma unroll
    for (int i = 0; i < 8; i++)
#pragma unroll
        for (int j = 0; j < 8; j++) acc[i][j] = 0.f;

    for (int k0 = 0; k0 < 2048; k0 += 16) {
#pragma unroll
        for (int i = 0; i < 2; i++) {
            int q   = tid + (i << 8);
            int row = q >> 2;
            int kq  = (q & 3) << 2;
            float4 va = *(const float4 *)(x + (size_t)(bm + row) * 2048 + k0 + kq);
            As[kq + 0][row] = va.x; As[kq + 1][row] = va.y;
            As[kq + 2][row] = va.z; As[kq + 3][row] = va.w;
            float4 vb = *(const float4 *)(W + (size_t)(bn + row) * 2048 + k0 + kq);
            Bs[kq + 0][row] = vb.x; Bs[kq + 1][row] = vb.y;
            Bs[kq + 2][row] = vb.z; Bs[kq + 3][row] = vb.w;
        }
        __syncthreads();
#pragma unroll
        for (int k = 0; k < 16; k++) {
            float a[8], bvv[8];
            *(float4 *)(a)     = *(const float4 *)&As[k][tr];
            *(float4 *)(a + 4) = *(const float4 *)&As[k][tr + 4];
            *(float4 *)(bvv)     = *(const float4 *)&Bs[k][tc];
            *(float4 *)(bvv + 4) = *(const float4 *)&Bs[k][tc + 4];
#pragma unroll
            for (int i = 0; i < 8; i++)
#pragma unroll
                for (int j = 0; j < 8; j++) acc[i][j] += a[i] * bvv[j];
        }
        __syncthreads();
    }

    float bj[8];
#pragma unroll
    for (int j = 0; j < 8; j++) bj[j] = __ldg(&bias[bn + tc + j]);
#pragma unroll
    for (int i = 0; i < 8; i++) {
        float4 v0 = make_float4(acc[i][0] + bj[0], acc[i][1] + bj[1],
                                acc[i][2] + bj[2], acc[i][3] + bj[3]);
        float4 v1 = make_float4(acc[i][4] + bj[4], acc[i][5] + bj[5],
                                acc[i][6] + bj[6], acc[i][7] + bj[7]);
        size_t off = (size_t)(bm + tr + i) * 2048 + bn + tc;
        *(float4 *)(C + off)     = v0;
        *(float4 *)(C + off + 4) = v1;
    }
}

// ------------------------------------------------------------------
// Persistent scan: barrier-free tagged dataflow.
// 148 blocks (1/SM, smem-pinned so all co-resident). Each block owns
// 13-14 rows of Wfh/Whf in SMEM. Per phase, consumers poll tagged
// 8B quads (value+generation in one atomic load) -- detection and
// data transfer collapse into a single L2 round trip. Double-buffered
// by step parity; pipeline lag bounds make reuse race-free.
// ------------------------------------------------------------------
__global__ __launch_bounds__(TPB, 1) void mgu_scan(
    const float* __restrict__ h0,
    const float* __restrict__ Wfh, const float* __restrict__ bfh,
    const float* __restrict__ Whf, const float* __restrict__ bhf,
    float* __restrict__ out)
{
    extern __shared__ float sW[];
    __shared__ float sPart[MAXR][8];
    __shared__ float sF[MAXR];
    __shared__ float sHold[MAXR];
    __shared__ float sBfh[MAXR];
    __shared__ float sBhf[MAXR];
    __shared__ unsigned sBase;

    const int b   = blockIdx.x;
    const int tid = threadIdx.x;
    const int r0  = (b * Hn) / NBLK;
    const int r1  = ((b + 1) * Hn) / NBLK;
    const int nr  = r1 - r0;               // 13 or 14

    float* sWf = sW;                        // Wfh rows
    float* sWh = sW + nr * Hn;              // Whf rows

    if (tid == 0) sBase = *(volatile unsigned *)&d_runbase;

    {   // stage weight rows into SMEM (coalesced float4)
        const float4* gf = (const float4 *)(Wfh + (size_t)r0 * Hn);
        const float4* gh = (const float4 *)(Whf + (size_t)r0 * Hn);
        float4* sf4 = (float4 *)sWf;
        float4* sh4 = (float4 *)sWh;
        const int n4 = nr * (Hn / 4);
        for (int i = tid; i < n4; i += TPB) { sf4[i] = gf[i]; sh4[i] = gh[i]; }
    }
    if (tid < nr) {
        sBfh[tid]  = bfh[r0 + tid];
        sBhf[tid]  = bhf[r0 + tid];
        sHold[tid] = h0[r0 + tid];
    }
    __syncthreads();
    const unsigned base = sBase;

    // publish initial hidden state (tag = base, buffer 0)
    if (tid < nr) st_quad(&d_hq[0][r0 + tid], sHold[tid], base);

    const int lane = tid & 31;
    const int wid  = tid >> 5;
    const int cA   = wid * 128 + lane * 4;          // conflict-free chunk 0
    const int cB   = 1024 + wid * 128 + lane * 4;   // conflict-free chunk 1

    // prefetch xf/xh for t=0
    float xf_c = 0.f, xh_c = 0.f;
    if (tid < nr) {
        xf_c = __ldg(&d_XF[r0 + tid]);
        xh_c = __ldg(&d_XH[r0 + tid]);
    }

    for (int t = 0; t < SEQ; t++) {
        const unsigned tag = base + (unsigned)t;

        // ===== phase A : f = sigmoid(xf + Wfh h + bfh);  g = f*h =====
        float hv[8];
        poll8(d_hq[t & 1], cA, cB, tag, hv);

        float acc[MAXR];
#pragma unroll
        for (int r = 0; r < MAXR; r++) {
            float a = 0.f;
            if (r < nr) {
                const float4* wp = (const float4 *)(sWf + r * Hn + cA);
                const float4* wq = (const float4 *)(sWf + r * Hn + cB);
                float4 w0 = wp[0], w1 = wq[0];
                a = w0.x * hv[0] + w0.y * hv[1] + w0.z * hv[2] + w0.w * hv[3]
                  + w1.x * hv[4] + w1.y * hv[5] + w1.z * hv[6] + w1.w * hv[7];
            }
            acc[r] = a;
        }
        // paired butterfly reduction: 6 SHFL per 2 rows
#pragma unroll
        for (int p = 0; p < 7; p++) {
            float a = acc[2 * p], c = acc[2 * p + 1];
            a += __shfl_xor_sync(0xffffffffu, a, 16);
            c += __shfl_xor_sync(0xffffffffu, c, 16);
            float m = (lane < 16) ? a : c;
            m += __shfl_xor_sync(0xffffffffu, m, 8);
            m += __shfl_xor_sync(0xffffffffu, m, 4);
            m += __shfl_xor_sync(0xffffffffu, m, 2);
            m += __shfl_xor_sync(0xffffffffu, m, 1);
            if (lane == 0)       sPart[2 * p][wid]     = m;
            else if (lane == 16) sPart[2 * p + 1][wid] = m;
        }
        __syncthreads();
        if (tid < nr) {
            float4 p0 = *(const float4 *)&sPart[tid][0];
            float4 p1 = *(const float4 *)&sPart[tid][4];
            float s = (p0.x + p0.y) + (p0.z + p0.w)
                    + (p1.x + p1.y) + (p1.z + p1.w);
            float z = s + sBfh[tid] + xf_c;
            float f = 1.f / (1.f + __expf(-z));
            sF[tid] = f;
            st_quad(&d_gq[t & 1][r0 + tid], f * sHold[tid], tag);
        }
        // (no barrier: consumers' g-poll blocks until our tail stores land;
        //  tail's sPart reads precede its g stores, so sPart reuse is safe)

        // ===== phase B : h_hat = tanh(Whf g + bhf + xh); update =====
        float gv[8];
        poll8(d_gq[t & 1], cA, cB, tag, gv);

        float xf_n = 0.f, xh_n = 0.f;                // prefetch next x-projections
        if (tid < nr && t + 1 < SEQ) {
            xf_n = __ldg(&d_XF[(size_t)(t + 1) * Hn + r0 + tid]);
            xh_n = __ldg(&d_XH[(size_t)(t + 1) * Hn + r0 + tid]);
        }

#pragma unroll
        for (int r = 0; r < MAXR; r++) {
            float a = 0.f;
            if (r < nr) {
                const float4* wp = (const float4 *)(sWh + r * Hn + cA);
                const float4* wq = (const float4 *)(sWh + r * Hn + cB);
                float4 w0 = wp[0], w1 = wq[0];
                a = w0.x * gv[0] + w0.y * gv[1] + w0.z * gv[2] + w0.w * gv[3]
                  + w1.x * gv[4] + w1.y * gv[5] + w1.z * gv[6] + w1.w * gv[7];
            }
            acc[r] = a;
        }
#pragma unroll
        for (int p = 0; p < 7; p++) {
            float a = acc[2 * p], c = acc[2 * p + 1];
            a += __shfl_xor_sync(0xffffffffu, a, 16);
            c += __shfl_xor_sync(0xffffffffu, c, 16);
            float m = (lane < 16) ? a : c;
            m += __shfl_xor_sync(0xffffffffu, m, 8);
            m += __shfl_xor_sync(0xffffffffu, m, 4);
            m += __shfl_xor_sync(0xffffffffu, m, 2);
            m += __shfl_xor_sync(0xffffffffu, m, 1);
            if (lane == 0)       sPart[2 * p][wid]     = m;
            else if (lane == 16) sPart[2 * p + 1][wid] = m;
        }
        __syncthreads();
        if (tid < nr) {
            float4 p0 = *(const float4 *)&sPart[tid][0];
            float4 p1 = *(const float4 *)&sPart[tid][4];
            float s = (p0.x + p0.y) + (p0.z + p0.w)
                    + (p1.x + p1.y) + (p1.z + p1.w);
            float z  = s + sBhf[tid] + xh_c;
            float e2 = __expf(2.f * z);
            float hh = 1.f - 2.f / (e2 + 1.f);      // tanh(z)
            float f  = sF[tid];
            float ho = sHold[tid];
            float hn = ho + f * (hh - ho);          // (1-f)*h + f*h_hat
            sHold[tid] = hn;
            int row = r0 + tid;
            out[(size_t)t * Hn + row] = hn;
            st_quad(&d_hq[(t + 1) & 1][row], hn, tag + 1);  // next step's h
            if (t == SEQ - 1) out[(size_t)SEQ * Hn + row] = hn;  // h_final
        }
        xf_c = xf_n;
        xh_c = xh_n;
    }

    // advance tag base for the next graph replay (block 0 finishes only
    // after consuming every other block's final publishes)
    if (b == 0 && tid == 0)
        *(volatile unsigned *)&d_runbase = base + (unsigned)SEQ + 1u;
}

// ------------------------------------------------------------------
extern "C" void kernel_launch(void* const* d_in, const int* in_sizes, int n_in,
                              void* d_out, int out_size)
{
    const float* x   = (const float *)d_in[0];
    const float* h0  = (const float *)d_in[1];
    const float* Wfx = (const float *)d_in[2];
    const float* bfx = (const float *)d_in[3];
    const float* Wfh = (const float *)d_in[4];
    const float* bfh = (const float *)d_in[5];
    const float* Whf = (const float *)d_in[6];
    const float* bhf = (const float *)d_in[7];
    const float* Whx = (const float *)d_in[8];
    const float* bhx = (const float *)d_in[9];
    float* out = (float *)d_out;

    (void)in_sizes; (void)n_in; (void)out_size;

    const size_t smem = (size_t)MAXR * Hn * 2 * sizeof(float);  // 229376 B
    cudaFuncSetAttribute(mgu_scan, cudaFuncAttributeMaxDynamicSharedMemorySize,
                         (int)smem);

    mgu_gemm<<<dim3(16, 16, 2), 256>>>(x, Wfx, bfx, Whx, bhx);
    mgu_scan<<<NBLK, TPB, smem>>>(h0, Wfh, bfh, Whf, bhf, out);
}

// round 9
// speedup vs baseline: 2.7803x; 2.7803x over previous
#include <cuda_runtime.h>
#include <math.h>

#define Hn   2048
#define SEQ  2048
#define NBLK 148
#define TPB  288     // 8 worker warps (256) + 1 poller warp
#define WTH  256
#define MAXR 14      // max rows per block: ceil(2048/148)
#define NCNT 32      // striped barrier counters

// ------------------------------------------------------------------
// Static device scratch (no cudaMalloc allowed)
// ------------------------------------------------------------------
struct alignas(128) PadCnt { unsigned v; unsigned pad[31]; };

__device__ float d_XF[SEQ * Hn];   // x @ Wfx^T + bfx
__device__ float d_XH[SEQ * Hn];   // x @ Whx^T + bhx
__device__ float d_hbuf[Hn];       // hidden state (cross-block)
__device__ float d_gbuf[Hn];       // f * h (cross-block)
__device__ PadCnt  d_cnt[NCNT];    // striped arrival counters (zero-init)
__device__ unsigned d_base = 0;    // sum of counters at start of this run

__device__ __forceinline__ void red_arrive(unsigned* p) {
    asm volatile("red.release.gpu.global.add.u32 [%0], %1;"
                 :: "l"(p), "r"(1u) : "memory");
}
__device__ __forceinline__ unsigned ld_rlx(const unsigned* p) {
    unsigned v;
    asm volatile("ld.relaxed.gpu.global.u32 %0, [%1];" : "=r"(v) : "l"(p) : "memory");
    return v;
}
__device__ __forceinline__ void fence_acq() {
    asm volatile("fence.acq_rel.gpu;" ::: "memory");
}
// workers-only barrier
__device__ __forceinline__ void bar1() {
    asm volatile("bar.sync 1, %0;" :: "n"(WTH) : "memory");
}
// workers + poller barrier
__device__ __forceinline__ void bar2() {
    asm volatile("bar.sync 2, %0;" :: "n"(TPB) : "memory");
}
// sum all striped counters with full MLP (32 independent L2 lines)
__device__ __forceinline__ unsigned sum_cnt() {
    unsigned s = 0;
#pragma unroll
    for (int i = 0; i < NCNT; i++) s += ld_rlx(&d_cnt[i].v);
    return s;
}

// ------------------------------------------------------------------
// Precompute GEMM:  C[s][n] = sum_k x[s][k] * W[n][k] + bias[n]
// ------------------------------------------------------------------
__global__ __launch_bounds__(256, 2) void mgu_gemm(
    const float* __restrict__ x,
    const float* __restrict__ Wfx, const float* __restrict__ bfx,
    const float* __restrict__ Whx, const float* __restrict__ bhx)
{
    const float* __restrict__ W    = (blockIdx.z == 0) ? Wfx : Whx;
    const float* __restrict__ bias = (blockIdx.z == 0) ? bfx : bhx;
    float* __restrict__ C          = (blockIdx.z == 0) ? d_XF : d_XH;

    __shared__ float As[16][132];
    __shared__ float Bs[16][132];

    const int bm  = blockIdx.y * 128;
    const int bn  = blockIdx.x * 128;
    const int tid = threadIdx.x;
    const int tr  = (tid >> 4) << 3;
    const int tc  = (tid & 15) << 3;

    float acc[8][8];
#pragma unroll
    for (int i = 0; i < 8; i++)
#pragma unroll
        for (int j = 0; j < 8; j++) acc[i][j] = 0.f;

    for (int k0 = 0; k0 < 2048; k0 += 16) {
#pragma unroll
        for (int i = 0; i < 2; i++) {
            int q   = tid + (i << 8);
            int row = q >> 2;
            int kq  = (q & 3) << 2;
            float4 va = *(const float4 *)(x + (size_t)(bm + row) * 2048 + k0 + kq);
            As[kq + 0][row] = va.x; As[kq + 1][row] = va.y;
            As[kq + 2][row] = va.z; As[kq + 3][row] = va.w;
            float4 vb = *(const float4 *)(W + (size_t)(bn + row) * 2048 + k0 + kq);
            Bs[kq + 0][row] = vb.x; Bs[kq + 1][row] = vb.y;
            Bs[kq + 2][row] = vb.z; Bs[kq + 3][row] = vb.w;
        }
        __syncthreads();
#pragma unroll
        for (int k = 0; k < 16; k++) {
            float a[8], bvv[8];
            *(float4 *)(a)     = *(const float4 *)&As[k][tr];
            *(float4 *)(a + 4) = *(const float4 *)&As[k][tr + 4];
            *(float4 *)(bvv)     = *(const float4 *)&Bs[k][tc];
            *(float4 *)(bvv + 4) = *(const float4 *)&Bs[k][tc + 4];
#pragma unroll
            for (int i = 0; i < 8; i++)
#pragma unroll
                for (int j = 0; j < 8; j++) acc[i][j] += a[i] * bvv[j];
        }
        __syncthreads();
    }

    float bj[8];
#pragma unroll
    for (int j = 0; j < 8; j++) bj[j] = __ldg(&bias[bn + tc + j]);
#pragma unroll
    for (int i = 0; i < 8; i++) {
        float4 v0 = make_float4(acc[i][0] + bj[0], acc[i][1] + bj[1],
                                acc[i][2] + bj[2], acc[i][3] + bj[3]);
        float4 v1 = make_float4(acc[i][4] + bj[4], acc[i][5] + bj[5],
                                acc[i][6] + bj[6], acc[i][7] + bj[7]);
        size_t off = (size_t)(bm + tr + i) * 2048 + bn + tc;
        *(float4 *)(C + off)     = v0;
        *(float4 *)(C + off + 4) = v1;
    }
}

// ------------------------------------------------------------------
// Persistent scan. 148 blocks (1/SM). Warps 0-7 = workers, warp 8 =
// poller. Arrival RED striped over 32 L2 lines (no single-line
// hotspot); poller sums all 32 with relaxed loads (MLP=32) and
// upgrades with an acquire fence before releasing workers.
// ------------------------------------------------------------------
__global__ __launch_bounds__(TPB, 1) void mgu_scan(
    const float* __restrict__ h0,
    const float* __restrict__ Wfh, const float* __restrict__ bfh,
    const float* __restrict__ Whf, const float* __restrict__ bhf,
    float* __restrict__ out)
{
    extern __shared__ float sW[];
    __shared__ float sPart[MAXR][8];
    __shared__ float sF[MAXR];
    __shared__ float sHold[MAXR];
    __shared__ float sBfh[MAXR];
    __shared__ float sBhf[MAXR];
    __shared__ unsigned sBase;

    const int b   = blockIdx.x;
    const int tid = threadIdx.x;
    const int r0  = (b * Hn) / NBLK;
    const int r1  = ((b + 1) * Hn) / NBLK;
    const int nr  = r1 - r0;               // 13 or 14

    float* sWf = sW;                        // Wfh rows
    float* sWh = sW + nr * Hn;              // Whf rows

    if (tid == 0) sBase = *(volatile unsigned *)&d_base;

    {   // stage weight rows into SMEM (coalesced float4)
        const float4* gf = (const float4 *)(Wfh + (size_t)r0 * Hn);
        const float4* gh = (const float4 *)(Whf + (size_t)r0 * Hn);
        float4* sf4 = (float4 *)sWf;
        float4* sh4 = (float4 *)sWh;
        const int n4 = nr * (Hn / 4);
        for (int i = tid; i < n4; i += TPB) { sf4[i] = gf[i]; sh4[i] = gh[i]; }
    }
    if (tid < nr) {
        sBfh[tid]  = bfh[r0 + tid];
        sBhf[tid]  = bhf[r0 + tid];
        sHold[tid] = h0[r0 + tid];
    }
    for (int i = b * TPB + tid; i < Hn; i += NBLK * TPB) d_hbuf[i] = h0[i];

    __syncthreads();
    const unsigned base = sBase;
    unsigned* myCnt = &d_cnt[b & (NCNT - 1)].v;
    if (tid == 0) red_arrive(myCnt);         // gen 1: weights + h0 published

    // ---------------- poller warp ----------------
    if (tid >= WTH) {
        for (unsigned g = 1; g <= 2u * SEQ; g++) {
            if (tid == WTH) {
                unsigned target = base + g * (unsigned)NBLK;
                while ((int)(sum_cnt() - target) < 0) { }
                fence_acq();
            }
            bar2();
        }
        if (b == 0 && tid == WTH)
            *(volatile unsigned *)&d_base = base + 2u * SEQ * (unsigned)NBLK;
        return;
    }

    // ---------------- workers ----------------
    const int lane = tid & 31;
    const int wid  = tid >> 5;
    const int cA   = wid * 128 + lane * 4;          // conflict-free chunk 0
    const int cB   = 1024 + wid * 128 + lane * 4;   // conflict-free chunk 1

    float xf_c = 0.f, xh_c = 0.f;
    if (tid < nr) {
        xf_c = __ldg(&d_XF[r0 + tid]);
        xh_c = __ldg(&d_XH[r0 + tid]);
    }

    float4 wr[MAXR][2];
#pragma unroll
    for (int r = 0; r < MAXR; r++) {                // preload Wfh for t=0
        wr[r][0] = *(const float4 *)(sWf + r * Hn + cA);
        wr[r][1] = *(const float4 *)(sWf + r * Hn + cB);
    }
    bar2();                                          // gen 1 synced: h ready

    for (int t = 0; t < SEQ; t++) {
        // ===== phase A : f = sigmoid(xf + Wfh h + bfh);  g = f*h =====
        float4 hv0 = __ldcg((const float4 *)&d_hbuf[cA]);
        float4 hv1 = __ldcg((const float4 *)&d_hbuf[cB]);

        float acc[MAXR];
#pragma unroll
        for (int r = 0; r < MAXR; r++) {
            acc[r] = wr[r][0].x * hv0.x + wr[r][0].y * hv0.y
                   + wr[r][0].z * hv0.z + wr[r][0].w * hv0.w
                   + wr[r][1].x * hv1.x + wr[r][1].y * hv1.y
                   + wr[r][1].z * hv1.z + wr[r][1].w * hv1.w;
        }
        // paired butterfly reduction: 6 SHFL per 2 rows
#pragma unroll
        for (int p = 0; p < 7; p++) {
            float a = acc[2 * p], c = acc[2 * p + 1];
            a += __shfl_xor_sync(0xffffffffu, a, 16);
            c += __shfl_xor_sync(0xffffffffu, c, 16);
            float m = (lane < 16) ? a : c;
            m += __shfl_xor_sync(0xffffffffu, m, 8);
            m += __shfl_xor_sync(0xffffffffu, m, 4);
            m += __shfl_xor_sync(0xffffffffu, m, 2);
            m += __shfl_xor_sync(0xffffffffu, m, 1);
            if (lane == 0)       sPart[2 * p][wid]     = m;
            else if (lane == 16) sPart[2 * p + 1][wid] = m;
        }
        bar1();
        if (tid < nr) {
            float4 p0 = *(const float4 *)&sPart[tid][0];
            float4 p1 = *(const float4 *)&sPart[tid][4];
            float s = (p0.x + p0.y) + (p0.z + p0.w)
                    + (p1.x + p1.y) + (p1.z + p1.w);
            float z = s + sBfh[tid] + xf_c;
            float f = 1.f / (1.f + __expf(-z));
            sF[tid] = f;
            __stcg(&d_gbuf[r0 + tid], f * sHold[tid]);
        }
        bar1();
        if (tid == 0) red_arrive(myCnt);             // gen 2t+2
#pragma unroll
        for (int r = 0; r < MAXR; r++) {             // preload Whf (hidden under sync)
            wr[r][0] = *(const float4 *)(sWh + r * Hn + cA);
            wr[r][1] = *(const float4 *)(sWh + r * Hn + cB);
        }
        bar2();                                      // gen 2t+2 synced: g ready

        // ===== phase B : h_hat = tanh(Whf g + bhf + xh); update =====
        float4 gv0 = __ldcg((const float4 *)&d_gbuf[cA]);
        float4 gv1 = __ldcg((const float4 *)&d_gbuf[cB]);

        float xf_n = 0.f, xh_n = 0.f;                // prefetch next x-projections
        if (tid < nr && t + 1 < SEQ) {
            xf_n = __ldg(&d_XF[(size_t)(t + 1) * Hn + r0 + tid]);
            xh_n = __ldg(&d_XH[(size_t)(t + 1) * Hn + r0 + tid]);
        }

#pragma unroll
        for (int r = 0; r < MAXR; r++) {
            acc[r] = wr[r][0].x * gv0.x + wr[r][0].y * gv0.y
                   + wr[r][0].z * gv0.z + wr[r][0].w * gv0.w
                   + wr[r][1].x * gv1.x + wr[r][1].y * gv1.y
                   + wr[r][1].z * gv1.z + wr[r][1].w * gv1.w;
        }
#pragma unroll
        for (int p = 0; p < 7; p++) {
            float a = acc[2 * p], c = acc[2 * p + 1];
            a += __shfl_xor_sync(0xffffffffu, a, 16);
            c += __shfl_xor_sync(0xffffffffu, c, 16);
            float m = (lane < 16) ? a : c;
            m += __shfl_xor_sync(0xffffffffu, m, 8);
            m += __shfl_xor_sync(0xffffffffu, m, 4);
            m += __shfl_xor_sync(0xffffffffu, m, 2);
            m += __shfl_xor_sync(0xffffffffu, m, 1);
            if (lane == 0)       sPart[2 * p][wid]     = m;
            else if (lane == 16) sPart[2 * p + 1][wid] = m;
        }
        bar1();
        if (tid < nr) {
            float4 p0 = *(const float4 *)&sPart[tid][0];
            float4 p1 = *(const float4 *)&sPart[tid][4];
            float s = (p0.x + p0.y) + (p0.z + p0.w)
                    + (p1.x + p1.y) + (p1.z + p1.w);
            float z  = s + sBhf[tid] + xh_c;
            float e2 = __expf(2.f * z);
            float hh = 1.f - 2.f / (e2 + 1.f);      // tanh(z)
            float f  = sF[tid];
            float ho = sHold[tid];
            float hn = ho + f * (hh - ho);          // (1-f)*h + f*h_hat
            sHold[tid] = hn;
            int row = r0 + tid;
            out[(size_t)t * Hn + row] = hn;
            __stcg(&d_hbuf[row], hn);
            if (t == SEQ - 1) out[(size_t)SEQ * Hn + row] = hn;  // h_final
        }
        bar1();
        if (t < SEQ - 1) {
            if (tid == 0) red_arrive(myCnt);         // gen 2t+3
#pragma unroll
            for (int r = 0; r < MAXR; r++) {         // preload Wfh for next step
                wr[r][0] = *(const float4 *)(sWf + r * Hn + cA);
                wr[r][1] = *(const float4 *)(sWf + r * Hn + cB);
            }
            bar2();                                  // gen 2t+3 synced: h ready
        }
        xf_c = xf_n;
        xh_c = xh_n;
    }
}

// ------------------------------------------------------------------
extern "C" void kernel_launch(void* const* d_in, const int* in_sizes, int n_in,
                              void* d_out, int out_size)
{
    const float* x   = (const float *)d_in[0];
    const float* h0  = (const float *)d_in[1];
    const float* Wfx = (const float *)d_in[2];
    const float* bfx = (const float *)d_in[3];
    const float* Wfh = (const float *)d_in[4];
    const float* bfh = (const float *)d_in[5];
    const float* Whf = (const float *)d_in[6];
    const float* bhf = (const float *)d_in[7];
    const float* Whx = (const float *)d_in[8];
    const float* bhx = (const float *)d_in[9];
    float* out = (float *)d_out;

    (void)in_sizes; (void)n_in; (void)out_size;

    const size_t smem = (size_t)MAXR * Hn * 2 * sizeof(float);  // 229376 B
    cudaFuncSetAttribute(mgu_scan, cudaFuncAttributeMaxDynamicSharedMemorySize,
                         (int)smem);

    mgu_gemm<<<dim3(16, 16, 2), 256>>>(x, Wfx, bfx, Whx, bhx);
    mgu_scan<<<NBLK, TPB, smem>>>(h0, Wfh, bfh, Whf, bhf, out);
}

// round 10
// speedup vs baseline: 3.0012x; 1.0794x over previous
#include <cuda_runtime.h>
#include <math.h>

#define Hn   2048
#define SEQ  2048
#define NBLK 148
#define TPB  288     // 8 worker warps (256) + 1 poller warp
#define WTH  256
#define MAXR 14      // max rows per block: ceil(2048/148)

// ------------------------------------------------------------------
// Static device scratch (no cudaMalloc allowed)
// ------------------------------------------------------------------
__device__ float d_XF[SEQ * Hn];   // x @ Wfx^T + bfx
__device__ float d_XH[SEQ * Hn];   // x @ Whx^T + bhx
__device__ float d_hbuf[Hn];       // hidden state (cross-block)
__device__ float d_gbuf[Hn];       // f * h (cross-block)
__device__ unsigned d_count = 0;   // monotonic barrier arrival counter
__device__ unsigned d_base  = 0;   // counter value at start of this run

__device__ __forceinline__ void red_arrive(unsigned* p) {
    asm volatile("red.release.gpu.global.add.u32 [%0], %1;"
                 :: "l"(p), "r"(1u) : "memory");
}
__device__ __forceinline__ unsigned ld_acq(const unsigned* p) {
    unsigned v;
    asm volatile("ld.acquire.gpu.global.u32 %0, [%1];" : "=r"(v) : "l"(p) : "memory");
    return v;
}
// workers-only barrier
__device__ __forceinline__ void bar1() {
    asm volatile("bar.sync 1, %0;" :: "n"(WTH) : "memory");
}
// workers + poller barrier
__device__ __forceinline__ void bar2() {
    asm volatile("bar.sync 2, %0;" :: "n"(TPB) : "memory");
}

// ------------------------------------------------------------------
// Precompute GEMM:  C[s][n] = sum_k x[s][k] * W[n][k] + bias[n]
// ------------------------------------------------------------------
__global__ __launch_bounds__(256, 2) void mgu_gemm(
    const float* __restrict__ x,
    const float* __restrict__ Wfx, const float* __restrict__ bfx,
    const float* __restrict__ Whx, const float* __restrict__ bhx)
{
    const float* __restrict__ W    = (blockIdx.z == 0) ? Wfx : Whx;
    const float* __restrict__ bias = (blockIdx.z == 0) ? bfx : bhx;
    float* __restrict__ C          = (blockIdx.z == 0) ? d_XF : d_XH;

    __shared__ float As[16][132];
    __shared__ float Bs[16][132];

    const int bm  = blockIdx.y * 128;
    const int bn  = blockIdx.x * 128;
    const int tid = threadIdx.x;
    const int tr  = (tid >> 4) << 3;
    const int tc  = (tid & 15) << 3;

    float acc[8][8];
#pragma unroll
    for (int i = 0; i < 8; i++)
#pragma unroll
        for (int j = 0; j < 8; j++) acc[i][j] = 0.f;

    for (int k0 = 0; k0 < 2048; k0 += 16) {
#pragma unroll
        for (int i = 0; i < 2; i++) {
            int q   = tid + (i << 8);
            int row = q >> 2;
            int kq  = (q & 3) << 2;
            float4 va = *(const float4 *)(x + (size_t)(bm + row) * 2048 + k0 + kq);
            As[kq + 0][row] = va.x; As[kq + 1][row] = va.y;
            As[kq + 2][row] = va.z; As[kq + 3][row] = va.w;
            float4 vb = *(const float4 *)(W + (size_t)(bn + row) * 2048 + k0 + kq);
            Bs[kq + 0][row] = vb.x; Bs[kq + 1][row] = vb.y;
            Bs[kq + 2][row] = vb.z; Bs[kq + 3][row] = vb.w;
        }
        __syncthreads();
#pragma unroll
        for (int k = 0; k < 16; k++) {
            float a[8], bvv[8];
            *(float4 *)(a)     = *(const float4 *)&As[k][tr];
            *(float4 *)(a + 4) = *(const float4 *)&As[k][tr + 4];
            *(float4 *)(bvv)     = *(const float4 *)&Bs[k][tc];
            *(float4 *)(bvv + 4) = *(const float4 *)&Bs[k][tc + 4];
#pragma unroll
            for (int i = 0; i < 8; i++)
#pragma unroll
                for (int j = 0; j < 8; j++) acc[i][j] += a[i] * bvv[j];
        }
        __syncthreads();
    }

    float bj[8];
#pragma unroll
    for (int j = 0; j < 8; j++) bj[j] = __ldg(&bias[bn + tc + j]);
#pragma unroll
    for (int i = 0; i < 8; i++) {
        float4 v0 = make_float4(acc[i][0] + bj[0], acc[i][1] + bj[1],
                                acc[i][2] + bj[2], acc[i][3] + bj[3]);
        float4 v1 = make_float4(acc[i][4] + bj[4], acc[i][5] + bj[5],
                                acc[i][6] + bj[6], acc[i][7] + bj[7]);
        size_t off = (size_t)(bm + tr + i) * 2048 + bn + tc;
        *(float4 *)(C + off)     = v0;
        *(float4 *)(C + off + 4) = v1;
    }
}

// ------------------------------------------------------------------
// Persistent scan. 148 blocks (1/SM). Warps 0-7 = workers, warp 8 =
// poller (single counter, ld.acquire poll, NO fences).
// Wfh is REGISTER-RESIDENT for the whole kernel (112 regs/thread):
// phase A does zero shared-memory traffic and the B->A barrier
// window is empty. Whf streams from SMEM during phase B's GEMV.
// ------------------------------------------------------------------
__global__ __launch_bounds__(TPB, 1) void mgu_scan(
    const float* __restrict__ h0,
    const float* __restrict__ Wfh, const float* __restrict__ bfh,
    const float* __restrict__ Whf, const float* __restrict__ bhf,
    float* __restrict__ out)
{
    extern __shared__ float sWh[];          // Whf rows only (112 KB)
    __shared__ float sPart[MAXR][8];
    __shared__ float sF[MAXR];
    __shared__ float sHold[MAXR];
    __shared__ float sBfh[MAXR];
    __shared__ float sBhf[MAXR];
    __shared__ unsigned sBase;

    const int b   = blockIdx.x;
    const int tid = threadIdx.x;
    const int r0  = (b * Hn) / NBLK;
    const int r1  = ((b + 1) * Hn) / NBLK;
    const int nr  = r1 - r0;               // 13 or 14

    if (tid == 0) sBase = *(volatile unsigned *)&d_base;

    {   // stage Whf rows into SMEM (coalesced float4)
        const float4* gh = (const float4 *)(Whf + (size_t)r0 * Hn);
        float4* sh4 = (float4 *)sWh;
        const int n4 = nr * (Hn / 4);
        for (int i = tid; i < n4; i += TPB) sh4[i] = gh[i];
    }
    if (tid < nr) {
        sBfh[tid]  = bfh[r0 + tid];
        sBhf[tid]  = bhf[r0 + tid];
        sHold[tid] = h0[r0 + tid];
    }
    for (int i = b * TPB + tid; i < Hn; i += NBLK * TPB) d_hbuf[i] = h0[i];

    __syncthreads();
    const unsigned base = sBase;
    if (tid == 0) red_arrive(&d_count);      // gen 1: weights + h0 published

    // ---------------- poller warp ----------------
    if (tid >= WTH) {
        for (unsigned g = 1; g <= 2u * SEQ; g++) {
            if (tid == WTH) {
                unsigned target = base + g * (unsigned)NBLK;
                while ((int)(ld_acq(&d_count) - target) < 0) { }
            }
            bar2();
        }
        if (b == 0 && tid == WTH)
            *(volatile unsigned *)&d_base = base + 2u * SEQ * (unsigned)NBLK;
        return;
    }

    // ---------------- workers ----------------
    const int lane = tid & 31;
    const int wid  = tid >> 5;
    const int cA   = wid * 128 + lane * 4;          // conflict-free chunk 0
    const int cB   = 1024 + wid * 128 + lane * 4;   // conflict-free chunk 1

    // Wfh: register-resident for the whole kernel (one-time GMEM load)
    float4 wf[MAXR][2];
#pragma unroll
    for (int r = 0; r < MAXR; r++) {
        int rr = (r < nr) ? r : nr - 1;              // clamp (avoid OOB)
        wf[r][0] = __ldg((const float4 *)(Wfh + (size_t)(r0 + rr) * Hn + cA));
        wf[r][1] = __ldg((const float4 *)(Wfh + (size_t)(r0 + rr) * Hn + cB));
    }

    float xf_c = 0.f, xh_c = 0.f;
    if (tid < nr) {
        xf_c = __ldg(&d_XF[r0 + tid]);
        xh_c = __ldg(&d_XH[r0 + tid]);
    }

    bar2();                                          // gen 1 synced: h ready

    for (int t = 0; t < SEQ; t++) {
        // ===== phase A : f = sigmoid(xf + Wfh h + bfh);  g = f*h =====
        float4 hv0 = __ldcg((const float4 *)&d_hbuf[cA]);
        float4 hv1 = __ldcg((const float4 *)&d_hbuf[cB]);

        float acc[MAXR];
#pragma unroll
        for (int r = 0; r < MAXR; r++) {
            acc[r] = wf[r][0].x * hv0.x + wf[r][0].y * hv0.y
                   + wf[r][0].z * hv0.z + wf[r][0].w * hv0.w
                   + wf[r][1].x * hv1.x + wf[r][1].y * hv1.y
                   + wf[r][1].z * hv1.z + wf[r][1].w * hv1.w;
        }
        // paired butterfly reduction: 6 SHFL per 2 rows
#pragma unroll
        for (int p = 0; p < 7; p++) {
            float a = acc[2 * p], c = acc[2 * p + 1];
            a += __shfl_xor_sync(0xffffffffu, a, 16);
            c += __shfl_xor_sync(0xffffffffu, c, 16);
            float m = (lane < 16) ? a : c;
            m += __shfl_xor_sync(0xffffffffu, m, 8);
            m += __shfl_xor_sync(0xffffffffu, m, 4);
            m += __shfl_xor_sync(0xffffffffu, m, 2);
            m += __shfl_xor_sync(0xffffffffu, m, 1);
            if (lane == 0)       sPart[2 * p][wid]     = m;
            else if (lane == 16) sPart[2 * p + 1][wid] = m;
        }
        bar1();
        if (tid < 32) {                              // tail lives in warp 0
            if (tid < nr) {
                float4 p0 = *(const float4 *)&sPart[tid][0];
                float4 p1 = *(const float4 *)&sPart[tid][4];
                float s = (p0.x + p0.y) + (p0.z + p0.w)
                        + (p1.x + p1.y) + (p1.z + p1.w);
                float z = s + sBfh[tid] + xf_c;
                float f = 1.f / (1.f + __expf(-z));
                sF[tid] = f;
                __stcg(&d_gbuf[r0 + tid], f * sHold[tid]);
            }
            __syncwarp();
            if (tid == 0) red_arrive(&d_count);      // gen 2t+2
        }
        bar2();                                      // gen 2t+2 synced: g ready

        // ===== phase B : h_hat = tanh(Whf g + bhf + xh); update =====
        float4 gv0 = __ldcg((const float4 *)&d_gbuf[cA]);
        float4 gv1 = __ldcg((const float4 *)&d_gbuf[cB]);

        float xf_n = 0.f, xh_n = 0.f;                // prefetch next x-projections
        if (tid < nr && t + 1 < SEQ) {
            xf_n = __ldg(&d_XF[(size_t)(t + 1) * Hn + r0 + tid]);
            xh_n = __ldg(&d_XH[(size_t)(t + 1) * Hn + r0 + tid]);
        }

#pragma unroll
        for (int r = 0; r < MAXR; r++) {             // Whf streamed from SMEM
            const float4 w0 = *(const float4 *)(sWh + r * Hn + cA);
            const float4 w1 = *(const float4 *)(sWh + r * Hn + cB);
            acc[r] = w0.x * gv0.x + w0.y * gv0.y + w0.z * gv0.z + w0.w * gv0.w
                   + w1.x * gv1.x + w1.y * gv1.y + w1.z * gv1.z + w1.w * gv1.w;
        }
#pragma unroll
        for (int p = 0; p < 7; p++) {
            float a = acc[2 * p], c = acc[2 * p + 1];
            a += __shfl_xor_sync(0xffffffffu, a, 16);
            c += __shfl_xor_sync(0xffffffffu, c, 16);
            float m = (lane < 16) ? a : c;
            m += __shfl_xor_sync(0xffffffffu, m, 8);
            m += __shfl_xor_sync(0xffffffffu, m, 4);
            m += __shfl_xor_sync(0xffffffffu, m, 2);
            m += __shfl_xor_sync(0xffffffffu, m, 1);
            if (lane == 0)       sPart[2 * p][wid]     = m;
            else if (lane == 16) sPart[2 * p + 1][wid] = m;
        }
        bar1();
        if (tid < 32) {
            if (tid < nr) {
                float4 p0 = *(const float4 *)&sPart[tid][0];
                float4 p1 = *(const float4 *)&sPart[tid][4];
                float s = (p0.x + p0.y) + (p0.z + p0.w)
                        + (p1.x + p1.y) + (p1.z + p1.w);
                float z  = s + sBhf[tid] + xh_c;
                float e2 = __expf(2.f * z);
                float hh = 1.f - 2.f / (e2 + 1.f);      // tanh(z)
                float f  = sF[tid];
                float ho = sHold[tid];
                float hn = ho + f * (hh - ho);          // (1-f)*h + f*h_hat
                sHold[tid] = hn;
                int row = r0 + tid;
                out[(size_t)t * Hn + row] = hn;
                __stcg(&d_hbuf[row], hn);
                if (t == SEQ - 1) out[(size_t)SEQ * Hn + row] = hn;  // h_final
            }
            __syncwarp();
            if (tid == 0 && t < SEQ - 1) red_arrive(&d_count);   // gen 2t+3
        }
        if (t < SEQ - 1) bar2();                     // gen 2t+3 synced: h ready
        xf_c = xf_n;
        xh_c = xh_n;
    }
}

// ------------------------------------------------------------------
extern "C" void kernel_launch(void* const* d_in, const int* in_sizes, int n_in,
                              void* d_out, int out_size)
{
    const float* x   = (const float *)d_in[0];
    const float* h0  = (const float *)d_in[1];
    const float* Wfx = (const float *)d_in[2];
    const float* bfx = (const float *)d_in[3];
    const float* Wfh = (const float *)d_in[4];
    const float* bfh = (const float *)d_in[5];
    const float* Whf = (const float *)d_in[6];
    const float* bhf = (const float *)d_in[7];
    const float* Whx = (const float *)d_in[8];
    const float* bhx = (const float *)d_in[9];
    float* out = (float *)d_out;

    (void)in_sizes; (void)n_in; (void)out_size;

    const size_t smem = (size_t)MAXR * Hn * sizeof(float);  // 114688 B (Whf only)
    cudaFuncSetAttribute(mgu_scan, cudaFuncAttributeMaxDynamicSharedMemorySize,
                         (int)smem);

    mgu_gemm<<<dim3(16, 16, 2), 256>>>(x, Wfx, bfx, Whx, bhx);
    mgu_scan<<<NBLK, TPB, smem>>>(h0, Wfh, bfh, Whf, bhf, out);
}